// round 12
// baseline (speedup 1.0000x reference)
#include <cuda_runtime.h>
#include <cuda_fp16.h>
#include <cstdint>

// ---------------------------------------------------------------- problem
#define BATCH  8192
#define IN_F   1024
#define OUT_F  1024
#define NB     11
#define KDIM   (IN_F * 12)          // 12288 halves of augmented K
#define BKF    8                    // features per chunk
#define BK     (BKF * 12)           // 96 halves per chunk
#define BKW    (BK / 2)             // 48 u32 words per row per chunk
#define NITER  (IN_F / BKF)         // 128 chunks total
#define KSPLIT 4
#define NQ     (NITER / KSPLIT)     // 32 chunks per K-quarter
#define BM     128
#define BN     128
#define THREADS 256

// smem (u32 words): A and B tiles [row][k-words], stride 52 (48 data + 4 pad)
#define SK     52
#define TBUF   (128 * SK)           // 6656 words per tile buffer
#define SMEM_BYTES (4 * TBUF * 4)   // 106496 B -> 2 CTAs/SM

// ---------------------------------------------------------------- scratch
__device__ uint32_t g_Wh[(size_t)OUT_F * (KDIM / 2)];       // fp16-pair weights [o][kw]
__device__ float    g_part[(size_t)KSPLIT * BATCH * OUT_F]; // split-K partials (128MB)

// ---------------------------------------------------------------- helpers
__device__ __forceinline__ uint32_t smem_u32(const void* p) {
    uint32_t a;
    asm("{ .reg .u64 t; cvta.to.shared.u64 t, %1; cvt.u32.u64 %0, t; }" : "=r"(a) : "l"(p));
    return a;
}
#define CP_ASYNC16(d, s) asm volatile("cp.async.cg.shared.global [%0], [%1], 16;" :: "r"(d), "l"(s) : "memory")
#define CP_COMMIT()      asm volatile("cp.async.commit_group;" ::: "memory")
#define CP_WAIT0()       asm volatile("cp.async.wait_group 0;" ::: "memory")

#define LDSM_X4(r0, r1, r2, r3, addr)                                         \
    asm volatile("ldmatrix.sync.aligned.m8n8.x4.shared.b16 {%0,%1,%2,%3}, [%4];" \
                 : "=r"(r0), "=r"(r1), "=r"(r2), "=r"(r3) : "r"(addr))

#define MMA_F16(d, a, b)                                                      \
    asm volatile(                                                             \
        "mma.sync.aligned.m16n8k16.row.col.f32.f16.f16.f32 "                  \
        "{%0,%1,%2,%3}, {%4,%5,%6,%7}, {%8,%9}, {%0,%1,%2,%3};\n"             \
        : "+f"((d)[0]), "+f"((d)[1]), "+f"((d)[2]), "+f"((d)[3])              \
        : "r"((a)[0]), "r"((a)[1]), "r"((a)[2]), "r"((a)[3]),                 \
          "r"((b)[0]), "r"((b)[1]))

__device__ __forceinline__ uint32_t packh2(float lo, float hi) {
    __half2 h = __floats2half2_rn(lo, hi);      // lo -> .x (even k)
    return *(uint32_t*)&h;
}

// silu + 11 cubic B-spline bases (fp32; fp16 rounding at pack)
__device__ __forceinline__ void gen12f(float x, float v[12]) {
    v[0] = x / (1.0f + __expf(-x));
#pragma unroll
    for (int k = 0; k < NB; k++) {
        float c  = -1.25f + 0.25f * (float)k;
        float u  = fabsf(x - c) * 4.0f;
        float c2 = 2.0f - u;
        float c1 = 1.0f - u;
        float c23 = c2 * c2 * c2;
        float inner = (c23 - 4.0f * c1 * c1 * c1) * (1.0f / 6.0f);
        float outer = c23 * (1.0f / 6.0f);
        v[k + 1] = (u < 1.0f) ? inner : ((u < 2.0f) ? outer : 0.0f);
    }
}

// ---------------------------------------------------------------- prep kernel
__global__ void prep_wh_kernel(const float* __restrict__ bw,
                               const float* __restrict__ sw) {
    int idx = blockIdx.x * blockDim.x + threadIdx.x;     // o*IN_F + i
    float v[12];
    v[0] = bw[idx];
    const float* sp = sw + (size_t)idx * NB;
#pragma unroll
    for (int j = 0; j < NB; j++) v[1 + j] = sp[j];
    uint32_t p[6];
#pragma unroll
    for (int j = 0; j < 6; j++) p[j] = packh2(v[2 * j], v[2 * j + 1]);
    uint2* dst = (uint2*)(g_Wh + (size_t)idx * 6);
    dst[0] = make_uint2(p[0], p[1]);
    dst[1] = make_uint2(p[2], p[3]);
    dst[2] = make_uint2(p[4], p[5]);
}

// ---------------------------------------------------------------- main GEMM (one K-quarter)
__global__ void __launch_bounds__(THREADS, 2) kan_gemm_kernel(const float* __restrict__ x) {
    extern __shared__ uint32_t sm[];
    uint32_t* As = sm;                    // [2][128][SK] rows = M
    uint32_t* Bs = sm + 2 * TBUF;         // [2][128][SK] rows = N
    const uint32_t as_b = smem_u32(As);
    const uint32_t bs_b = smem_u32(Bs);

    const int t   = threadIdx.x;
    const int bn0 = blockIdx.x * BN;
    const int bm0 = blockIdx.y * BM;
    const int kz  = blockIdx.z;           // K-quarter
    const int it0 = kz * NQ;              // first chunk of this quarter

    // staging roles
    const int rloc = t & 127;             // A row this thread generates
    const int fh   = t >> 7;              // handles features fh*4 .. fh*4+3
    const int brow = t >> 1;              // B row (out column)
    const int bsel = (t & 1) * 6;

    // direct x access: 4 consecutive features of one row = one float4
    const float*    xrow = x + (size_t)(bm0 + rloc) * IN_F + fh * 4;
    const uint32_t* wrow = g_Wh + (size_t)(bn0 + brow) * (KDIM / 2);
    const uint32_t  bdst0 = bs_b + (brow * SK) * 4 + bsel * 16;

    // mma roles
    const int lane = t & 31, wid = t >> 5;
    const int wm0 = (wid >> 1) * 32;
    const int wn0 = (wid & 1) * 64;
    const int g  = lane >> 2, t4 = lane & 3;

    // ldmatrix per-lane addresses
    const int la7 = lane & 7, sel = lane >> 3;
    const uint32_t aAddr0 = as_b +
        (((wm0 + la7 + (sel & 1) * 8) * SK) + (sel >> 1) * 4) * 4;
    const uint32_t bAddr0 = bs_b +
        (((wn0 + la7 + (sel >> 1) * 8) * SK) + (sel & 1) * 4) * 4;

    float acc[2][8][4];
#pragma unroll
    for (int mt = 0; mt < 2; mt++)
#pragma unroll
        for (int nt = 0; nt < 8; nt++)
#pragma unroll
            for (int q = 0; q < 4; q++) acc[mt][nt][q] = 0.0f;

    auto stageB = [&](int ic, int nb) {   // ic = absolute chunk index
        const char* src = (const char*)(wrow + (size_t)ic * BKW) + bsel * 16;
        uint32_t dst = bdst0 + nb * (TBUF * 4);
#pragma unroll
        for (int c = 0; c < 6; c++)
            CP_ASYNC16(dst + c * 16, src + c * 16);
        CP_COMMIT();
    };

    auto genA = [&](float4 xv, int nb) {
        uint32_t* aptr = As + nb * TBUF + rloc * SK + fh * 24;
        float xs[4] = {xv.x, xv.y, xv.z, xv.w};
#pragma unroll
        for (int f = 0; f < 4; f++) {
            float v[12];
            gen12f(xs[f], v);
            uint2* d = (uint2*)(aptr + f * 6);
            d[0] = make_uint2(packh2(v[0], v[1]),  packh2(v[2], v[3]));
            d[1] = make_uint2(packh2(v[4], v[5]),  packh2(v[6], v[7]));
            d[2] = make_uint2(packh2(v[8], v[9]),  packh2(v[10], v[11]));
        }
    };

    // -------- prologue --------
    stageB(it0, 0);
    genA(*(const float4*)(xrow + it0 * BKF), 0);
    CP_WAIT0();
    __syncthreads();

    // -------- main loop over this K-quarter --------
    for (int j = 0; j < NQ; ++j) {
        const int it = it0 + j;
        const int cur = j & 1, nxt = cur ^ 1;
        const bool hn = (j + 1 < NQ);

        float4 xv;
        if (hn) {
            stageB(it + 1, nxt);
            xv = *(const float4*)(xrow + (it + 1) * BKF);
        }

        const uint32_t bufo = (uint32_t)(cur * TBUF * 4);
#pragma unroll
        for (int s = 0; s < 6; s++) {
            const uint32_t ko = bufo + s * 32;
            uint32_t af[2][4];
            LDSM_X4(af[0][0], af[0][1], af[0][2], af[0][3], aAddr0 + ko);
            LDSM_X4(af[1][0], af[1][1], af[1][2], af[1][3],
                    aAddr0 + ko + 16 * SK * 4);
            uint32_t bf[8][2];
#pragma unroll
            for (int ntp = 0; ntp < 4; ntp++)
                LDSM_X4(bf[2 * ntp][0], bf[2 * ntp][1],
                        bf[2 * ntp + 1][0], bf[2 * ntp + 1][1],
                        bAddr0 + ko + ntp * 16 * SK * 4);
#pragma unroll
            for (int mt = 0; mt < 2; mt++)
#pragma unroll
                for (int nt = 0; nt < 8; nt++)
                    MMA_F16(acc[mt][nt], af[mt], bf[nt]);
        }

        if (hn) genA(xv, nxt);

        CP_WAIT0();
        __syncthreads();
    }

    // -------- epilogue: store unclipped partials (deterministic slots) --------
    float* part = g_part + (size_t)kz * BATCH * OUT_F;
#pragma unroll
    for (int mt = 0; mt < 2; mt++) {
#pragma unroll
        for (int nt = 0; nt < 8; nt++) {
            int row = bm0 + wm0 + mt * 16 + g;
            int col = bn0 + wn0 + nt * 8 + t4 * 2;
            *(float2*)&part[(size_t)row * OUT_F + col] =
                make_float2(acc[mt][nt][0], acc[mt][nt][1]);
            *(float2*)&part[(size_t)(row + 8) * OUT_F + col] =
                make_float2(acc[mt][nt][2], acc[mt][nt][3]);
        }
    }
}

// ---------------------------------------------------------------- reduce + clip
__global__ void reduce_kernel(float* __restrict__ out) {
    size_t idx = ((size_t)blockIdx.x * blockDim.x + threadIdx.x) * 4;
    const size_t S = (size_t)BATCH * OUT_F;
    const float4 p0 = *(const float4*)&g_part[idx];
    const float4 p1 = *(const float4*)&g_part[S + idx];
    const float4 p2 = *(const float4*)&g_part[2 * S + idx];
    const float4 p3 = *(const float4*)&g_part[3 * S + idx];
    float4 r;
    r.x = fminf(fmaxf((p0.x + p1.x) + (p2.x + p3.x), -1.0f), 1.0f);
    r.y = fminf(fmaxf((p0.y + p1.y) + (p2.y + p3.y), -1.0f), 1.0f);
    r.z = fminf(fmaxf((p0.z + p1.z) + (p2.z + p3.z), -1.0f), 1.0f);
    r.w = fminf(fmaxf((p0.w + p1.w) + (p2.w + p3.w), -1.0f), 1.0f);
    *(float4*)&out[idx] = r;
}

// ---------------------------------------------------------------- launch
extern "C" void kernel_launch(void* const* d_in, const int* in_sizes, int n_in,
                              void* d_out, int out_size) {
    (void)in_sizes; (void)n_in; (void)out_size;
    const float* x  = (const float*)d_in[0];
    const float* bw = (const float*)d_in[1];
    const float* sw = (const float*)d_in[2];
    float* out = (float*)d_out;

    cudaFuncSetAttribute(kan_gemm_kernel,
                         cudaFuncAttributeMaxDynamicSharedMemorySize, SMEM_BYTES);

    prep_wh_kernel<<<(OUT_F * IN_F) / 256, 256>>>(bw, sw);
    kan_gemm_kernel<<<dim3(OUT_F / BN, BATCH / BM, KSPLIT), THREADS, SMEM_BYTES>>>(x);
    reduce_kernel<<<(BATCH * OUT_F) / (256 * 4), 256>>>(out);
}

// round 13
// speedup vs baseline: 1.0007x; 1.0007x over previous
#include <cuda_runtime.h>
#include <cuda_fp16.h>
#include <cstdint>

// ---------------------------------------------------------------- problem
#define BATCH  8192
#define IN_F   1024
#define OUT_F  1024
#define NB     11
#define KDIM   (IN_F * 12)          // 12288 halves of augmented K
#define BKF    8                    // features per chunk
#define BK     (BKF * 12)           // 96 halves per chunk
#define BKW    (BK / 2)             // 48 u32 words per row per chunk
#define NITER  (IN_F / BKF)         // 128 chunks total
#define KSPLIT 2
#define NQ     (NITER / KSPLIT)     // 64 chunks per K-half
#define BM     128
#define BN     128
#define THREADS 256

// smem (u32 words): A and B tiles [row][k-words], stride 52 (48 data + 4 pad)
#define SK     52
#define TBUF   (128 * SK)           // 6656 words per tile buffer
#define SMEM_BYTES (4 * TBUF * 4)   // 106496 B -> 2 CTAs/SM

// ---------------------------------------------------------------- scratch
__device__ uint32_t g_Wh[(size_t)OUT_F * (KDIM / 2)];       // fp16-pair weights [o][kw]
__device__ float    g_part[(size_t)KSPLIT * BATCH * OUT_F]; // split-K partials (64MB)

// ---------------------------------------------------------------- helpers
__device__ __forceinline__ uint32_t smem_u32(const void* p) {
    uint32_t a;
    asm("{ .reg .u64 t; cvta.to.shared.u64 t, %1; cvt.u32.u64 %0, t; }" : "=r"(a) : "l"(p));
    return a;
}
#define CP_ASYNC16(d, s) asm volatile("cp.async.cg.shared.global [%0], [%1], 16;" :: "r"(d), "l"(s) : "memory")
#define CP_COMMIT()      asm volatile("cp.async.commit_group;" ::: "memory")
#define CP_WAIT0()       asm volatile("cp.async.wait_group 0;" ::: "memory")

#define LDSM_X4(r0, r1, r2, r3, addr)                                         \
    asm volatile("ldmatrix.sync.aligned.m8n8.x4.shared.b16 {%0,%1,%2,%3}, [%4];" \
                 : "=r"(r0), "=r"(r1), "=r"(r2), "=r"(r3) : "r"(addr))

#define MMA_F16(d, a, b)                                                      \
    asm volatile(                                                             \
        "mma.sync.aligned.m16n8k16.row.col.f32.f16.f16.f32 "                  \
        "{%0,%1,%2,%3}, {%4,%5,%6,%7}, {%8,%9}, {%0,%1,%2,%3};\n"             \
        : "+f"((d)[0]), "+f"((d)[1]), "+f"((d)[2]), "+f"((d)[3])              \
        : "r"((a)[0]), "r"((a)[1]), "r"((a)[2]), "r"((a)[3]),                 \
          "r"((b)[0]), "r"((b)[1]))

__device__ __forceinline__ uint32_t packh2(float lo, float hi) {
    __half2 h = __floats2half2_rn(lo, hi);      // lo -> .x (even k)
    return *(uint32_t*)&h;
}

// silu + 11 cubic B-spline bases (fp32; fp16 rounding at pack)
__device__ __forceinline__ void gen12f(float x, float v[12]) {
    v[0] = x / (1.0f + __expf(-x));
#pragma unroll
    for (int k = 0; k < NB; k++) {
        float c  = -1.25f + 0.25f * (float)k;
        float u  = fabsf(x - c) * 4.0f;
        float c2 = 2.0f - u;
        float c1 = 1.0f - u;
        float c23 = c2 * c2 * c2;
        float inner = (c23 - 4.0f * c1 * c1 * c1) * (1.0f / 6.0f);
        float outer = c23 * (1.0f / 6.0f);
        v[k + 1] = (u < 1.0f) ? inner : ((u < 2.0f) ? outer : 0.0f);
    }
}

// ---------------------------------------------------------------- prep kernel
__global__ void prep_wh_kernel(const float* __restrict__ bw,
                               const float* __restrict__ sw) {
    int idx = blockIdx.x * blockDim.x + threadIdx.x;     // o*IN_F + i
    float v[12];
    v[0] = bw[idx];
    const float* sp = sw + (size_t)idx * NB;
#pragma unroll
    for (int j = 0; j < NB; j++) v[1 + j] = sp[j];
    uint32_t p[6];
#pragma unroll
    for (int j = 0; j < 6; j++) p[j] = packh2(v[2 * j], v[2 * j + 1]);
    uint2* dst = (uint2*)(g_Wh + (size_t)idx * 6);
    dst[0] = make_uint2(p[0], p[1]);
    dst[1] = make_uint2(p[2], p[3]);
    dst[2] = make_uint2(p[4], p[5]);
}

// ---------------------------------------------------------------- main GEMM (one K-half)
__global__ void __launch_bounds__(THREADS, 2) kan_gemm_kernel(const float* __restrict__ x) {
    extern __shared__ uint32_t sm[];
    uint32_t* As = sm;                    // [2][128][SK] rows = M
    uint32_t* Bs = sm + 2 * TBUF;         // [2][128][SK] rows = N
    const uint32_t as_b = smem_u32(As);
    const uint32_t bs_b = smem_u32(Bs);

    const int t   = threadIdx.x;
    const int bn0 = blockIdx.x * BN;
    const int bm0 = blockIdx.y * BM;
    const int kz  = blockIdx.z;           // K-half
    const int it0 = kz * NQ;              // first chunk of this half

    // staging roles
    const int rloc = t & 127;             // A row this thread generates
    const int fh   = t >> 7;              // handles features fh*4 .. fh*4+3
    const int brow = t >> 1;              // B row (out column)
    const int bsel = (t & 1) * 6;

    // direct x access: 4 consecutive features of one row = one float4
    const float*    xrow = x + (size_t)(bm0 + rloc) * IN_F + fh * 4;
    const uint32_t* wrow = g_Wh + (size_t)(bn0 + brow) * (KDIM / 2);
    const uint32_t  bdst0 = bs_b + (brow * SK) * 4 + bsel * 16;

    // mma roles
    const int lane = t & 31, wid = t >> 5;
    const int wm0 = (wid >> 1) * 32;
    const int wn0 = (wid & 1) * 64;
    const int g  = lane >> 2, t4 = lane & 3;

    // ldmatrix per-lane addresses
    const int la7 = lane & 7, sel = lane >> 3;
    const uint32_t aAddr0 = as_b +
        (((wm0 + la7 + (sel & 1) * 8) * SK) + (sel >> 1) * 4) * 4;
    const uint32_t bAddr0 = bs_b +
        (((wn0 + la7 + (sel >> 1) * 8) * SK) + (sel & 1) * 4) * 4;

    float acc[2][8][4];
#pragma unroll
    for (int mt = 0; mt < 2; mt++)
#pragma unroll
        for (int nt = 0; nt < 8; nt++)
#pragma unroll
            for (int q = 0; q < 4; q++) acc[mt][nt][q] = 0.0f;

    auto stageB = [&](int ic, int nb) {   // ic = absolute chunk index
        const char* src = (const char*)(wrow + (size_t)ic * BKW) + bsel * 16;
        uint32_t dst = bdst0 + nb * (TBUF * 4);
#pragma unroll
        for (int c = 0; c < 6; c++)
            CP_ASYNC16(dst + c * 16, src + c * 16);
        CP_COMMIT();
    };

    auto genA = [&](float4 xv, int nb) {
        uint32_t* aptr = As + nb * TBUF + rloc * SK + fh * 24;
        float xs[4] = {xv.x, xv.y, xv.z, xv.w};
#pragma unroll
        for (int f = 0; f < 4; f++) {
            float v[12];
            gen12f(xs[f], v);
            uint2* d = (uint2*)(aptr + f * 6);
            d[0] = make_uint2(packh2(v[0], v[1]),  packh2(v[2], v[3]));
            d[1] = make_uint2(packh2(v[4], v[5]),  packh2(v[6], v[7]));
            d[2] = make_uint2(packh2(v[8], v[9]),  packh2(v[10], v[11]));
        }
    };

    // -------- prologue --------
    stageB(it0, 0);
    genA(*(const float4*)(xrow + it0 * BKF), 0);
    CP_WAIT0();
    __syncthreads();

    // -------- main loop over this K-half --------
    for (int j = 0; j < NQ; ++j) {
        const int it = it0 + j;
        const int cur = j & 1, nxt = cur ^ 1;
        const bool hn = (j + 1 < NQ);

        float4 xv;
        if (hn) {
            stageB(it + 1, nxt);          // async; lands during MMA section
            xv = *(const float4*)(xrow + (it + 1) * BKF);
        }

        const uint32_t bufo = (uint32_t)(cur * TBUF * 4);
#pragma unroll
        for (int s = 0; s < 6; s++) {
            const uint32_t ko = bufo + s * 32;
            uint32_t af[2][4];
            LDSM_X4(af[0][0], af[0][1], af[0][2], af[0][3], aAddr0 + ko);
            LDSM_X4(af[1][0], af[1][1], af[1][2], af[1][3],
                    aAddr0 + ko + 16 * SK * 4);
            uint32_t bf[8][2];
#pragma unroll
            for (int ntp = 0; ntp < 4; ntp++)
                LDSM_X4(bf[2 * ntp][0], bf[2 * ntp][1],
                        bf[2 * ntp + 1][0], bf[2 * ntp + 1][1],
                        bAddr0 + ko + ntp * 16 * SK * 4);
#pragma unroll
            for (int mt = 0; mt < 2; mt++)
#pragma unroll
                for (int nt = 0; nt < 8; nt++)
                    MMA_F16(acc[mt][nt], af[mt], bf[nt]);
        }

        if (hn) genA(xv, nxt);            // A for next chunk

        CP_WAIT0();
        __syncthreads();
    }

    // -------- epilogue: store unclipped partials (deterministic slots) --------
    float* part = g_part + (size_t)kz * BATCH * OUT_F;
#pragma unroll
    for (int mt = 0; mt < 2; mt++) {
#pragma unroll
        for (int nt = 0; nt < 8; nt++) {
            int row = bm0 + wm0 + mt * 16 + g;
            int col = bn0 + wn0 + nt * 8 + t4 * 2;
            *(float2*)&part[(size_t)row * OUT_F + col] =
                make_float2(acc[mt][nt][0], acc[mt][nt][1]);
            *(float2*)&part[(size_t)(row + 8) * OUT_F + col] =
                make_float2(acc[mt][nt][2], acc[mt][nt][3]);
        }
    }
}

// ---------------------------------------------------------------- reduce + clip
__global__ void reduce_kernel(float* __restrict__ out) {
    size_t idx = ((size_t)blockIdx.x * blockDim.x + threadIdx.x) * 4;
    const size_t S = (size_t)BATCH * OUT_F;
    const float4 p0 = *(const float4*)&g_part[idx];
    const float4 p1 = *(const float4*)&g_part[S + idx];
    float4 r;
    r.x = fminf(fmaxf(p0.x + p1.x, -1.0f), 1.0f);
    r.y = fminf(fmaxf(p0.y + p1.y, -1.0f), 1.0f);
    r.z = fminf(fmaxf(p0.z + p1.z, -1.0f), 1.0f);
    r.w = fminf(fmaxf(p0.w + p1.w, -1.0f), 1.0f);
    *(float4*)&out[idx] = r;
}

// ---------------------------------------------------------------- launch
extern "C" void kernel_launch(void* const* d_in, const int* in_sizes, int n_in,
                              void* d_out, int out_size) {
    (void)in_sizes; (void)n_in; (void)out_size;
    const float* x  = (const float*)d_in[0];
    const float* bw = (const float*)d_in[1];
    const float* sw = (const float*)d_in[2];
    float* out = (float*)d_out;

    cudaFuncSetAttribute(kan_gemm_kernel,
                         cudaFuncAttributeMaxDynamicSharedMemorySize, SMEM_BYTES);

    prep_wh_kernel<<<(OUT_F * IN_F) / 256, 256>>>(bw, sw);
    kan_gemm_kernel<<<dim3(OUT_F / BN, BATCH / BM, KSPLIT), THREADS, SMEM_BYTES>>>(x);
    reduce_kernel<<<(BATCH * OUT_F) / (256 * 4), 256>>>(out);
}

// round 15
// speedup vs baseline: 1.0391x; 1.0384x over previous
#include <cuda_runtime.h>
#include <cuda_fp16.h>
#include <cstdint>

// ---------------------------------------------------------------- problem
#define BATCH  8192
#define IN_F   1024
#define OUT_F  1024
#define NB     11
#define KDIM   (IN_F * 12)          // 12288 halves of augmented K
#define BKF    8                    // features per chunk
#define BK     (BKF * 12)           // 96 halves per chunk
#define BKW    (BK / 2)             // 48 u32 words per row per chunk
#define NITER  (IN_F / BKF)         // 128 chunks total
#define KSPLIT 2
#define NQ     (NITER / KSPLIT)     // 64 chunks per K-half
#define BM     128
#define BN     128
#define THREADS 256

// smem (u32 words): A and B tiles [row][k-words], stride 52 (48 data + 4 pad)
#define SK     52
#define TBUF   (128 * SK)           // 6656 words per tile buffer
#define SMEM_BYTES (4 * TBUF * 4)   // 106496 B -> 2 CTAs/SM

// fused prep grid split
#define PREP_WH_BLOCKS (OUT_F * IN_F / 256)            // 4096
#define PREP_TR_BLOCKS ((IN_F / 32) * (BATCH / 32))    // 8192

// ---------------------------------------------------------------- scratch
__device__ uint32_t g_Wh[(size_t)OUT_F * (KDIM / 2)];       // fp16-pair weights [o][kw]
__device__ float    g_xT[(size_t)IN_F * BATCH];             // x transposed [i][b]
__device__ float    g_part[(size_t)KSPLIT * BATCH * OUT_F]; // split-K partials (64MB)

// ---------------------------------------------------------------- helpers
__device__ __forceinline__ uint32_t smem_u32(const void* p) {
    uint32_t a;
    asm("{ .reg .u64 t; cvta.to.shared.u64 t, %1; cvt.u32.u64 %0, t; }" : "=r"(a) : "l"(p));
    return a;
}
#define CP_ASYNC16(d, s) asm volatile("cp.async.cg.shared.global [%0], [%1], 16;" :: "r"(d), "l"(s) : "memory")
#define CP_COMMIT()      asm volatile("cp.async.commit_group;" ::: "memory")
#define CP_WAIT0()       asm volatile("cp.async.wait_group 0;" ::: "memory")

#define LDSM_X4(r0, r1, r2, r3, addr)                                         \
    asm volatile("ldmatrix.sync.aligned.m8n8.x4.shared.b16 {%0,%1,%2,%3}, [%4];" \
                 : "=r"(r0), "=r"(r1), "=r"(r2), "=r"(r3) : "r"(addr))

#define MMA_F16(d, a, b)                                                      \
    asm volatile(                                                             \
        "mma.sync.aligned.m16n8k16.row.col.f32.f16.f16.f32 "                  \
        "{%0,%1,%2,%3}, {%4,%5,%6,%7}, {%8,%9}, {%0,%1,%2,%3};\n"             \
        : "+f"((d)[0]), "+f"((d)[1]), "+f"((d)[2]), "+f"((d)[3])              \
        : "r"((a)[0]), "r"((a)[1]), "r"((a)[2]), "r"((a)[3]),                 \
          "r"((b)[0]), "r"((b)[1]))

// streaming (evict-first) 8B store / 16B load for single-use partials
__device__ __forceinline__ void stcs8(float* p, float a, float b) {
    asm volatile("st.global.cs.v2.f32 [%0], {%1, %2};" :: "l"(p), "f"(a), "f"(b) : "memory");
}
__device__ __forceinline__ float4 ldcs16(const float* p) {
    float4 v;
    asm volatile("ld.global.cs.v4.f32 {%0,%1,%2,%3}, [%4];"
                 : "=f"(v.x), "=f"(v.y), "=f"(v.z), "=f"(v.w) : "l"(p));
    return v;
}

__device__ __forceinline__ uint32_t packh2(float lo, float hi) {
    __half2 h = __floats2half2_rn(lo, hi);      // lo -> .x (even k)
    return *(uint32_t*)&h;
}

// silu + 11 cubic B-spline bases (fp32; fp16 rounding at pack)
__device__ __forceinline__ void gen12f(float x, float v[12]) {
    v[0] = x / (1.0f + __expf(-x));
#pragma unroll
    for (int k = 0; k < NB; k++) {
        float c  = -1.25f + 0.25f * (float)k;
        float u  = fabsf(x - c) * 4.0f;
        float c2 = 2.0f - u;
        float c1 = 1.0f - u;
        float c23 = c2 * c2 * c2;
        float inner = (c23 - 4.0f * c1 * c1 * c1) * (1.0f / 6.0f);
        float outer = c23 * (1.0f / 6.0f);
        v[k + 1] = (u < 1.0f) ? inner : ((u < 2.0f) ? outer : 0.0f);
    }
}

// ---------------------------------------------------------------- fused prep
// blocks [0, PREP_WH_BLOCKS)                : pack weights to fp16 pairs
// blocks [PREP_WH_BLOCKS, +PREP_TR_BLOCKS)  : transpose x into g_xT
__global__ void prep_fused_kernel(const float* __restrict__ bw,
                                  const float* __restrict__ sw,
                                  const float* __restrict__ x) {
    if (blockIdx.x < PREP_WH_BLOCKS) {
        int idx = blockIdx.x * 256 + threadIdx.x;        // o*IN_F + i
        float v[12];
        v[0] = bw[idx];
        const float* sp = sw + (size_t)idx * NB;
#pragma unroll
        for (int j = 0; j < NB; j++) v[1 + j] = sp[j];
        uint32_t p[6];
#pragma unroll
        for (int j = 0; j < 6; j++) p[j] = packh2(v[2 * j], v[2 * j + 1]);
        uint2* dst = (uint2*)(g_Wh + (size_t)idx * 6);
        dst[0] = make_uint2(p[0], p[1]);
        dst[1] = make_uint2(p[2], p[3]);
        dst[2] = make_uint2(p[4], p[5]);
    } else {
        __shared__ float tile[32][33];
        int bid = blockIdx.x - PREP_WH_BLOCKS;
        int i0 = (bid % (IN_F / 32)) * 32;
        int b0 = (bid / (IN_F / 32)) * 32;
        int tx = threadIdx.x & 31, ty = threadIdx.x >> 5;  // 32x8
#pragma unroll
        for (int r = 0; r < 32; r += 8)
            tile[ty + r][tx] = x[(size_t)(b0 + ty + r) * IN_F + i0 + tx];
        __syncthreads();
#pragma unroll
        for (int r = 0; r < 32; r += 8)
            g_xT[(size_t)(i0 + ty + r) * BATCH + b0 + tx] = tile[tx][ty + r];
    }
}

// ---------------------------------------------------------------- main GEMM (one K-half)
__global__ void __launch_bounds__(THREADS, 2) kan_gemm_kernel() {
    extern __shared__ uint32_t sm[];
    uint32_t* As = sm;                    // [2][128][SK] rows = M
    uint32_t* Bs = sm + 2 * TBUF;         // [2][128][SK] rows = N
    const uint32_t as_b = smem_u32(As);
    const uint32_t bs_b = smem_u32(Bs);

    const int t   = threadIdx.x;
    const int bn0 = blockIdx.x * BN;
    const int bm0 = blockIdx.y * BM;
    const int kz  = blockIdx.z;           // K-half
    const int it0 = kz * NQ;              // first chunk of this half

    // staging roles
    const int rloc = t & 127;             // A row this thread generates
    const int fh   = t >> 7;              // handles features fh*4 .. fh*4+3
    const int brow = t >> 1;              // B row (out column)
    const int bsel = (t & 1) * 6;

    const float*    xbase = g_xT + bm0 + rloc;   // + i*BATCH indexes feature i
    const uint32_t* wrow  = g_Wh + (size_t)(bn0 + brow) * (KDIM / 2);
    const uint32_t  bdst0 = bs_b + (brow * SK) * 4 + bsel * 16;

    // mma roles
    const int lane = t & 31, wid = t >> 5;
    const int wm0 = (wid >> 1) * 32;
    const int wn0 = (wid & 1) * 64;
    const int g  = lane >> 2, t4 = lane & 3;

    // ldmatrix per-lane addresses
    const int la7 = lane & 7, sel = lane >> 3;
    const uint32_t aAddr0 = as_b +
        (((wm0 + la7 + (sel & 1) * 8) * SK) + (sel >> 1) * 4) * 4;
    const uint32_t bAddr0 = bs_b +
        (((wn0 + la7 + (sel >> 1) * 8) * SK) + (sel & 1) * 4) * 4;

    float acc[2][8][4];
#pragma unroll
    for (int mt = 0; mt < 2; mt++)
#pragma unroll
        for (int nt = 0; nt < 8; nt++)
#pragma unroll
            for (int q = 0; q < 4; q++) acc[mt][nt][q] = 0.0f;

    auto stageB = [&](int ic, int nb) {   // ic = absolute chunk index
        const char* src = (const char*)(wrow + (size_t)ic * BKW) + bsel * 16;
        uint32_t dst = bdst0 + nb * (TBUF * 4);
#pragma unroll
        for (int c = 0; c < 6; c++)
            CP_ASYNC16(dst + c * 16, src + c * 16);
        CP_COMMIT();
    };

    auto genA = [&](const float* xv, int nb) {
        uint32_t* aptr = As + nb * TBUF + rloc * SK + fh * 24;
#pragma unroll
        for (int f = 0; f < 4; f++) {
            float v[12];
            gen12f(xv[f], v);
            uint2* d = (uint2*)(aptr + f * 6);
            d[0] = make_uint2(packh2(v[0], v[1]),  packh2(v[2], v[3]));
            d[1] = make_uint2(packh2(v[4], v[5]),  packh2(v[6], v[7]));
            d[2] = make_uint2(packh2(v[8], v[9]),  packh2(v[10], v[11]));
        }
    };

    // -------- prologue --------
    stageB(it0, 0);
    {
        float xv[4];
#pragma unroll
        for (int f = 0; f < 4; f++)
            xv[f] = xbase[(size_t)(it0 * BKF + fh * 4 + f) * BATCH];
        genA(xv, 0);
    }
    CP_WAIT0();
    __syncthreads();

    // -------- main loop over this K-half --------
    for (int j = 0; j < NQ; ++j) {
        const int it = it0 + j;
        const int cur = j & 1, nxt = cur ^ 1;
        const bool hn = (j + 1 < NQ);

        float xv[4];
        if (hn) {
            stageB(it + 1, nxt);          // async; lands during MMA section
#pragma unroll
            for (int f = 0; f < 4; f++)
                xv[f] = xbase[(size_t)((it + 1) * BKF + fh * 4 + f) * BATCH];
        }

        const uint32_t bufo = (uint32_t)(cur * TBUF * 4);
#pragma unroll
        for (int s = 0; s < 6; s++) {
            const uint32_t ko = bufo + s * 32;
            uint32_t af[2][4];
            LDSM_X4(af[0][0], af[0][1], af[0][2], af[0][3], aAddr0 + ko);
            LDSM_X4(af[1][0], af[1][1], af[1][2], af[1][3],
                    aAddr0 + ko + 16 * SK * 4);
            uint32_t bf[8][2];
#pragma unroll
            for (int ntp = 0; ntp < 4; ntp++)
                LDSM_X4(bf[2 * ntp][0], bf[2 * ntp][1],
                        bf[2 * ntp + 1][0], bf[2 * ntp + 1][1],
                        bAddr0 + ko + ntp * 16 * SK * 4);
#pragma unroll
            for (int mt = 0; mt < 2; mt++)
#pragma unroll
                for (int nt = 0; nt < 8; nt++)
                    MMA_F16(acc[mt][nt], af[mt], bf[nt]);
        }

        if (hn) genA(xv, nxt);            // A for next chunk

        CP_WAIT0();
        __syncthreads();
    }

    // -------- epilogue: streaming-store unclipped partials --------
    float* part = g_part + (size_t)kz * BATCH * OUT_F;
#pragma unroll
    for (int mt = 0; mt < 2; mt++) {
#pragma unroll
        for (int nt = 0; nt < 8; nt++) {
            int row = bm0 + wm0 + mt * 16 + g;
            int col = bn0 + wn0 + nt * 8 + t4 * 2;
            stcs8(&part[(size_t)row * OUT_F + col],       acc[mt][nt][0], acc[mt][nt][1]);
            stcs8(&part[(size_t)(row + 8) * OUT_F + col], acc[mt][nt][2], acc[mt][nt][3]);
        }
    }
}

// ---------------------------------------------------------------- reduce + clip
__global__ void reduce_kernel(float* __restrict__ out) {
    size_t idx = ((size_t)blockIdx.x * blockDim.x + threadIdx.x) * 4;
    const size_t S = (size_t)BATCH * OUT_F;
    const float4 p0 = ldcs16(&g_part[idx]);
    const float4 p1 = ldcs16(&g_part[S + idx]);
    float4 r;
    r.x = fminf(fmaxf(p0.x + p1.x, -1.0f), 1.0f);
    r.y = fminf(fmaxf(p0.y + p1.y, -1.0f), 1.0f);
    r.z = fminf(fmaxf(p0.z + p1.z, -1.0f), 1.0f);
    r.w = fminf(fmaxf(p0.w + p1.w, -1.0f), 1.0f);
    *(float4*)&out[idx] = r;
}

// ---------------------------------------------------------------- launch
extern "C" void kernel_launch(void* const* d_in, const int* in_sizes, int n_in,
                              void* d_out, int out_size) {
    (void)in_sizes; (void)n_in; (void)out_size;
    const float* x  = (const float*)d_in[0];
    const float* bw = (const float*)d_in[1];
    const float* sw = (const float*)d_in[2];
    float* out = (float*)d_out;

    cudaFuncSetAttribute(kan_gemm_kernel,
                         cudaFuncAttributeMaxDynamicSharedMemorySize, SMEM_BYTES);

    prep_fused_kernel<<<PREP_WH_BLOCKS + PREP_TR_BLOCKS, 256>>>(bw, sw, x);
    kan_gemm_kernel<<<dim3(OUT_F / BN, BATCH / BM, KSPLIT), THREADS, SMEM_BYTES>>>();
    reduce_kernel<<<(BATCH * OUT_F) / (256 * 4), 256>>>(out);
}